// round 15
// baseline (speedup 1.0000x reference)
#include <cuda_runtime.h>

#define NW   17
#define NK   18     // padded k rows (row 17 zeroed)
#define CPAD 24     // padded col stride: j<9 -> col j ; j>=9 -> col j+3 (12..20)
#define JH   9      // j elements per thread (half, padded)
#define TPB  128

__device__ __forceinline__ float ex2_approx(float x) {
    float y; asm("ex2.approx.f32 %0, %1;" : "=f"(y) : "f"(x)); return y;
}
__device__ __forceinline__ float rcp_approx(float x) {
    float y; asm("rcp.approx.f32 %0, %1;" : "=f"(y) : "f"(x)); return y;
}
__device__ __forceinline__ float fast_tanh(float x) {
    float e = ex2_approx(x * 2.8853900817779268f);   // 2*log2(e)
    return fmaf(-2.0f, rcp_approx(e + 1.0f), 1.0f);
}

// Split-output matvec with FULL input vector v (no shuffles):
// acc[jj] (+)= sum_{k<17} v[k] * W[k][jb+jj]
template <bool INIT>
__device__ __forceinline__ void matvec_v(float acc[JH], const float v[NW],
                                         const float W[NK][CPAD], int jb) {
#pragma unroll
    for (int k = 0; k < NW; ++k) {
        const float vk = v[k];
        const float4* w4 = reinterpret_cast<const float4*>(&W[k][jb]);
        float4 w0 = w4[0], w1 = w4[1];
        float  w2 = W[k][jb + 8];
        if (INIT && k == 0) {
            acc[0] = vk * w0.x; acc[1] = vk * w0.y; acc[2] = vk * w0.z; acc[3] = vk * w0.w;
            acc[4] = vk * w1.x; acc[5] = vk * w1.y; acc[6] = vk * w1.z; acc[7] = vk * w1.w;
            acc[8] = vk * w2;
        } else {
            acc[0] = fmaf(vk, w0.x, acc[0]); acc[1] = fmaf(vk, w0.y, acc[1]);
            acc[2] = fmaf(vk, w0.z, acc[2]); acc[3] = fmaf(vk, w0.w, acc[3]);
            acc[4] = fmaf(vk, w1.x, acc[4]); acc[5] = fmaf(vk, w1.y, acc[5]);
            acc[6] = fmaf(vk, w1.z, acc[6]); acc[7] = fmaf(vk, w1.w, acc[7]);
            acc[8] = fmaf(vk, w2,   acc[8]);
        }
    }
}

// Split-output matvec with SPLIT input vector m (shuffle-gather from the pair):
// acc[jj] += sum_{k<18} m_full[k] * W[k][jb+jj], m_full gathered via shfl.
__device__ __forceinline__ void matvec_m(float acc[JH], const float mloc[JH],
                                         const float W[NK][CPAD], int jb,
                                         int srcE, int srcO) {
#pragma unroll
    for (int k = 0; k < NK; ++k) {
        const float mk = __shfl_sync(0xffffffffu, mloc[k % JH], (k < JH) ? srcE : srcO);
        const float4* w4 = reinterpret_cast<const float4*>(&W[k][jb]);
        float4 w0 = w4[0], w1 = w4[1];
        float  w2 = W[k][jb + 8];
        acc[0] = fmaf(mk, w0.x, acc[0]); acc[1] = fmaf(mk, w0.y, acc[1]);
        acc[2] = fmaf(mk, w0.z, acc[2]); acc[3] = fmaf(mk, w0.w, acc[3]);
        acc[4] = fmaf(mk, w1.x, acc[4]); acc[5] = fmaf(mk, w1.y, acc[5]);
        acc[6] = fmaf(mk, w1.z, acc[6]); acc[7] = fmaf(mk, w1.w, acc[7]);
        acc[8] = fmaf(mk, w2,   acc[8]);
    }
}

__device__ __forceinline__ void feat(float v[NW], float s,
                                     const float* sWf, const float* sbf) {
#pragma unroll
    for (int j = 0; j < NW; ++j) v[j] = fast_tanh(fmaf(s, sWf[j], sbf[j]));
}

// 2 threads per row (even: j=0..8, odd: j=9..16+pad).
// R14 (this structure, uncapped): 772us, DRAM=0.9%, regs=255, occ=12.2%,
// issue=52.6% -- ptxas consumed all 255 regs opportunistically (live set is
// only ~130 floats; no spills). Single change this round: cap at 3 CTAs/SM
// (170 regs) to lift occupancy 8->12 warps/SM. Unlike R6-R11 (true live set
// > cap -> demotion), this structure has real slack under 170.
extern "C" __global__ void __launch_bounds__(TPB, 3)
mp_kernel(const float* __restrict__ inp,
          const float* __restrict__ Wf,  const float* __restrict__ bf,
          const float* __restrict__ Wm,  const float* __restrict__ bm,
          const float* __restrict__ Wu,  const float* __restrict__ bu,
          const float* __restrict__ Wr,  const float* __restrict__ br,
          float* __restrict__ out, int B)
{
    __shared__ __align__(16) float sM1[NK][CPAD];   // Wm[:17]
    __shared__ __align__(16) float sM2[NK][CPAD];   // Wm[17:34]
    __shared__ __align__(16) float sU1[NK][CPAD];   // Wu[:17]
    __shared__ __align__(16) float sU2[NK][CPAD];   // Wu[17:34]
    __shared__ __align__(16) float sU34[NK][CPAD];  // Wu[34:51]+Wu[51:68]
    __shared__ float sWf[NW], sbf[NW];
    __shared__ __align__(16) float sbm_s[CPAD], sbu_s[CPAD], sWr_s[5 * CPAD];
    __shared__ float sbr;

    const int tid = threadIdx.x;

    // Zero everything padded first (pads MUST be 0 for correctness).
    for (int idx = tid; idx < NK * CPAD; idx += TPB) {
        int k = idx / CPAD, c = idx % CPAD;
        sM1[k][c] = 0.f; sM2[k][c] = 0.f;
        sU1[k][c] = 0.f; sU2[k][c] = 0.f; sU34[k][c] = 0.f;
    }
    for (int idx = tid; idx < CPAD; idx += TPB) { sbm_s[idx] = 0.f; sbu_s[idx] = 0.f; }
    for (int idx = tid; idx < 5 * CPAD; idx += TPB) sWr_s[idx] = 0.f;
    __syncthreads();

    for (int idx = tid; idx < NW * NW; idx += TPB) {
        int k = idx / NW, j = idx % NW;
        int c = (j < JH) ? j : j + 3;
        sM1[k][c]  = Wm[idx];
        sM2[k][c]  = Wm[NW * NW + idx];
        sU1[k][c]  = Wu[idx];
        sU2[k][c]  = Wu[NW * NW + idx];
        sU34[k][c] = Wu[2 * NW * NW + idx] + Wu[3 * NW * NW + idx];
    }
    if (tid < NW) {
        sWf[tid] = Wf[tid]; sbf[tid] = bf[tid];
        int c = (tid < JH) ? tid : tid + 3;
        sbm_s[c] = bm[tid]; sbu_s[c] = bu[tid];
    }
    for (int idx = tid; idx < 5 * NW; idx += TPB) {
        int n = idx / NW, j = idx % NW;
        int c = (j < JH) ? j : j + 3;
        sWr_s[n * CPAD + c] = Wr[idx];
    }
    if (tid == 0) sbr = br[0];
    __syncthreads();

    const int gtid = blockIdx.x * TPB + tid;
    const int row  = gtid >> 1;
    if (row >= B) return;

    const int lane = tid & 31;
    const int srcE = lane & ~1, srcO = srcE | 1;
    const int half = tid & 1;
    const int jb   = half * 12;     // col base: 0 (j 0..8) or 12 (j 9..16+pad)

    const float x0 = inp[row * 5 + 0];
    const float x1 = inp[row * 5 + 1];
    const float x2 = inp[row * 5 + 2];
    const float x3 = inp[row * 5 + 3];
    const float x4 = inp[row * 5 + 4];

    float o = half ? 0.f : sbr;
    float v[NW], m[JH];
    float Pa[JH], Qa[JH], Pb[JH], Qb[JH], Pc[JH], Qc[JH], Pd[JH], Qd[JH];
    float accA[JH], accB[JH], accC[JH], accD[JH];

    // ---- node a ----
    feat(v, x0, sWf, sbf);
    matvec_v<true>(Pa, v, sM1, jb);
    matvec_v<true>(Qa, v, sM2, jb);
#pragma unroll
    for (int jj = 0; jj < JH; ++jj) accA[jj] = sbu_s[jb + jj];
    matvec_v<false>(accA, v, sU34, jb);

    // ---- node b ----
    feat(v, x1, sWf, sbf);
    matvec_v<true>(Pb, v, sM1, jb);
    matvec_v<true>(Qb, v, sM2, jb);
#pragma unroll
    for (int jj = 0; jj < JH; ++jj) accB[jj] = sbu_s[jb + jj];
    matvec_v<false>(accB, v, sU34, jb);

    // ---- edges a-b ----
#pragma unroll
    for (int jj = 0; jj < JH; ++jj) m[jj] = fast_tanh(Pa[jj] + Qb[jj] + sbm_s[jb + jj]);
    matvec_m(accA, m, sU1, jb, srcE, srcO);                 // Mab
#pragma unroll
    for (int jj = 0; jj < JH; ++jj) m[jj] = fast_tanh(Pb[jj] + Qa[jj] + sbm_s[jb + jj]);
    matvec_m(accB, m, sU1, jb, srcE, srcO);                 // Mba

    // ---- node d ----
    feat(v, x3, sWf, sbf);
    matvec_v<true>(Pd, v, sM1, jb);
    matvec_v<true>(Qd, v, sM2, jb);
#pragma unroll
    for (int jj = 0; jj < JH; ++jj) accD[jj] = sbu_s[jb + jj];
    matvec_v<false>(accD, v, sU34, jb);

    // ---- edges a-d: retire node a ----
#pragma unroll
    for (int jj = 0; jj < JH; ++jj) m[jj] = fast_tanh(Pa[jj] + Qd[jj] + sbm_s[jb + jj]);
    matvec_m(accA, m, sU2, jb, srcE, srcO);                 // Mad (Pa dies)
#pragma unroll
    for (int jj = 0; jj < JH; ++jj) m[jj] = fast_tanh(Pd[jj] + Qa[jj] + sbm_s[jb + jj]);
    matvec_m(accD, m, sU2, jb, srcE, srcO);                 // Mda (Qa dies)
#pragma unroll
    for (int jj = 0; jj < JH; ++jj)
        o = fmaf(fast_tanh(accA[jj]), sWr_s[jb + jj], o);   // accA dies

    // ---- node c ----
    feat(v, x2, sWf, sbf);
    matvec_v<true>(Pc, v, sM1, jb);
    matvec_v<true>(Qc, v, sM2, jb);
#pragma unroll
    for (int jj = 0; jj < JH; ++jj) accC[jj] = sbu_s[jb + jj];
    matvec_v<false>(accC, v, sU34, jb);

    // ---- edges b-c: retire node b ----
#pragma unroll
    for (int jj = 0; jj < JH; ++jj) m[jj] = fast_tanh(Pb[jj] + Qc[jj] + sbm_s[jb + jj]);
    matvec_m(accB, m, sU2, jb, srcE, srcO);                 // Mbc (Pb dies)
#pragma unroll
    for (int jj = 0; jj < JH; ++jj) m[jj] = fast_tanh(Pc[jj] + Qb[jj] + sbm_s[jb + jj]);
    matvec_m(accC, m, sU1, jb, srcE, srcO);                 // Mcb (Qb dies)
#pragma unroll
    for (int jj = 0; jj < JH; ++jj)
        o = fmaf(fast_tanh(accB[jj]), sWr_s[CPAD + jb + jj], o);  // accB dies

    // ---- edges c-d: retire nodes c and d ----
#pragma unroll
    for (int jj = 0; jj < JH; ++jj) m[jj] = fast_tanh(Pc[jj] + Qd[jj] + sbm_s[jb + jj]);
    matvec_m(accC, m, sU2, jb, srcE, srcO);                 // Mcd
#pragma unroll
    for (int jj = 0; jj < JH; ++jj) m[jj] = fast_tanh(Pd[jj] + Qc[jj] + sbm_s[jb + jj]);
    matvec_m(accD, m, sU1, jb, srcE, srcO);                 // Mdc
#pragma unroll
    for (int jj = 0; jj < JH; ++jj)
        o = fmaf(fast_tanh(accC[jj]), sWr_s[2 * CPAD + jb + jj], o);
#pragma unroll
    for (int jj = 0; jj < JH; ++jj)
        o = fmaf(fast_tanh(accD[jj]), sWr_s[3 * CPAD + jb + jj], o);

    // ---- node e ----
    feat(v, x4, sWf, sbf);
#pragma unroll
    for (int jj = 0; jj < JH; ++jj) accA[jj] = sbu_s[jb + jj];   // reuse accA
    matvec_v<false>(accA, v, sU34, jb);
#pragma unroll
    for (int jj = 0; jj < JH; ++jj)
        o = fmaf(fast_tanh(accA[jj]), sWr_s[4 * CPAD + jb + jj], o);

    // ---- pair reduction: even lane writes ----
    o += __shfl_xor_sync(0xffffffffu, o, 1);
    if (!half) out[row] = o;
}

extern "C" void kernel_launch(void* const* d_in, const int* in_sizes, int n_in,
                              void* d_out, int out_size)
{
    const float* inp = (const float*)d_in[0];
    const float* Wf  = (const float*)d_in[1];
    const float* bf  = (const float*)d_in[2];
    const float* Wm  = (const float*)d_in[3];
    const float* bm  = (const float*)d_in[4];
    const float* Wu  = (const float*)d_in[5];
    const float* bu  = (const float*)d_in[6];
    const float* Wr  = (const float*)d_in[7];
    const float* br  = (const float*)d_in[8];
    float* out = (float*)d_out;

    const int B = in_sizes[0] / 5;
    const long long threads = 2LL * B;
    const int grid = (int)((threads + TPB - 1) / TPB);
    mp_kernel<<<grid, TPB>>>(inp, Wf, bf, Wm, bm, Wu, bu, Wr, br, out, B);
}

// round 16
// speedup vs baseline: 1.1722x; 1.1722x over previous
#include <cuda_runtime.h>

#define NW   17
#define NK   18     // padded k rows (row 17 zeroed)
#define CPAD 24     // padded col stride: j<9 -> col j ; j>=9 -> col j+3
#define JH   9      // j elements per thread (half, padded)
#define TPB  128

typedef unsigned long long ull;

__device__ __forceinline__ float ex2_approx(float x) {
    float y; asm("ex2.approx.f32 %0, %1;" : "=f"(y) : "f"(x)); return y;
}
__device__ __forceinline__ float rcp_approx(float x) {
    float y; asm("rcp.approx.f32 %0, %1;" : "=f"(y) : "f"(x)); return y;
}
__device__ __forceinline__ float fast_tanh(float x) {
    float e = ex2_approx(x * 2.8853900817779268f);   // 2*log2(e)
    return fmaf(-2.0f, rcp_approx(e + 1.0f), 1.0f);
}

// ---- packed f32x2 helpers (FFMA2 path: only reachable via PTX) ----
__device__ __forceinline__ ull pack_dup(float x) {
    ull r; unsigned u = __float_as_uint(x);
    asm("mov.b64 %0, {%1, %2};" : "=l"(r) : "r"(u), "r"(u)); return r;
}
__device__ __forceinline__ ull fma2(ull a, ull b, ull c) {
    ull d; asm("fma.rn.f32x2 %0, %1, %2, %3;" : "=l"(d) : "l"(a), "l"(b), "l"(c)); return d;
}
__device__ __forceinline__ ull mul2(ull a, ull b) {
    ull d; asm("mul.rn.f32x2 %0, %1, %2;" : "=l"(d) : "l"(a), "l"(b)); return d;
}
__device__ __forceinline__ ull add2(ull a, ull b) {
    ull d; asm("add.rn.f32x2 %0, %1, %2;" : "=l"(d) : "l"(a), "l"(b)); return d;
}
__device__ __forceinline__ void unpack2(ull v, float& lo, float& hi) {
    unsigned a, b; asm("mov.b64 {%0, %1}, %2;" : "=r"(a), "=r"(b) : "l"(v));
    lo = __uint_as_float(a); hi = __uint_as_float(b);
}

// packed half-row vector: j 0..7 in 4 f32x2 + 1 scalar (j=8)
struct V9 { ull q[4]; float s; };

// acc (+)= sum_{k<17} v[k] * W[k][jb..jb+8]   (packed FFMA2)
template <bool INIT>
__device__ __forceinline__ void matvec_v(V9& acc, const float v[NW],
                                         const float W[NK][CPAD], int jb) {
#pragma unroll
    for (int k = 0; k < NW; ++k) {
        const float vk = v[k];
        const ull vv = pack_dup(vk);
        const ulonglong2* w = reinterpret_cast<const ulonglong2*>(&W[k][jb]);
        ulonglong2 w01 = w[0], w23 = w[1];
        float w8 = W[k][jb + 8];
        if (INIT && k == 0) {
            acc.q[0] = mul2(vv, w01.x); acc.q[1] = mul2(vv, w01.y);
            acc.q[2] = mul2(vv, w23.x); acc.q[3] = mul2(vv, w23.y);
            acc.s = vk * w8;
        } else {
            acc.q[0] = fma2(vv, w01.x, acc.q[0]); acc.q[1] = fma2(vv, w01.y, acc.q[1]);
            acc.q[2] = fma2(vv, w23.x, acc.q[2]); acc.q[3] = fma2(vv, w23.y, acc.q[3]);
            acc.s = fmaf(vk, w8, acc.s);
        }
    }
}

// acc += sum_{k<18} m_full[k] * W[k][jb..jb+8]; m_full gathered via shfl
__device__ __forceinline__ void matvec_m(V9& acc, const float mloc[JH],
                                         const float W[NK][CPAD], int jb,
                                         int srcE, int srcO) {
#pragma unroll
    for (int k = 0; k < NK; ++k) {
        const float mk = __shfl_sync(0xffffffffu, mloc[k % JH], (k < JH) ? srcE : srcO);
        const ull mm = pack_dup(mk);
        const ulonglong2* w = reinterpret_cast<const ulonglong2*>(&W[k][jb]);
        ulonglong2 w01 = w[0], w23 = w[1];
        float w8 = W[k][jb + 8];
        acc.q[0] = fma2(mm, w01.x, acc.q[0]); acc.q[1] = fma2(mm, w01.y, acc.q[1]);
        acc.q[2] = fma2(mm, w23.x, acc.q[2]); acc.q[3] = fma2(mm, w23.y, acc.q[3]);
        acc.s = fmaf(mk, w8, acc.s);
    }
}

__device__ __forceinline__ void feat(float v[NW], float s,
                                     const float* sWf, const float* sbf) {
#pragma unroll
    for (int j = 0; j < NW; ++j) v[j] = fast_tanh(fmaf(s, sWf[j], sbf[j]));
}

// m = tanh((P + Q) + bm), same associativity as the scalar version
__device__ __forceinline__ void mkmsg(float m[JH], const V9& P, const V9& Q,
                                      const ull bm2[4], float bm8) {
#pragma unroll
    for (int i = 0; i < 4; ++i) {
        ull t = add2(add2(P.q[i], Q.q[i]), bm2[i]);
        float lo, hi; unpack2(t, lo, hi);
        m[2 * i]     = fast_tanh(lo);
        m[2 * i + 1] = fast_tanh(hi);
    }
    m[8] = fast_tanh(P.s + Q.s + bm8);
}

// o += sum_j tanh(acc[j]) * wr[j]
__device__ __forceinline__ float fold(const V9& acc, const float* wr, float o) {
#pragma unroll
    for (int i = 0; i < 4; ++i) {
        float lo, hi; unpack2(acc.q[i], lo, hi);
        o = fmaf(fast_tanh(lo), wr[2 * i],     o);
        o = fmaf(fast_tanh(hi), wr[2 * i + 1], o);
    }
    return fmaf(fast_tanh(acc.s), wr[8], o);
}

// 2 threads per row; uncapped (R15 re-proved any reg cap -> spills). Packed
// FFMA2 cuts matvec issue slots ~25-30% on the R14 winner (772us, issue=52.6%).
extern "C" __global__ void __launch_bounds__(TPB)
mp_kernel(const float* __restrict__ inp,
          const float* __restrict__ Wf,  const float* __restrict__ bf,
          const float* __restrict__ Wm,  const float* __restrict__ bm,
          const float* __restrict__ Wu,  const float* __restrict__ bu,
          const float* __restrict__ Wr,  const float* __restrict__ br,
          float* __restrict__ out, int B)
{
    __shared__ __align__(16) float sM1[NK][CPAD];   // Wm[:17]
    __shared__ __align__(16) float sM2[NK][CPAD];   // Wm[17:34]
    __shared__ __align__(16) float sU1[NK][CPAD];   // Wu[:17]
    __shared__ __align__(16) float sU2[NK][CPAD];   // Wu[17:34]
    __shared__ __align__(16) float sU34[NK][CPAD];  // Wu[34:51]+Wu[51:68]
    __shared__ float sWf[NW], sbf[NW];
    __shared__ __align__(16) float sbm_s[CPAD], sbu_s[CPAD], sWr_s[5 * CPAD];
    __shared__ float sbr;

    const int tid = threadIdx.x;

    // Zero padded regions first (pads MUST be 0).
    for (int idx = tid; idx < NK * CPAD; idx += TPB) {
        int k = idx / CPAD, c = idx % CPAD;
        sM1[k][c] = 0.f; sM2[k][c] = 0.f;
        sU1[k][c] = 0.f; sU2[k][c] = 0.f; sU34[k][c] = 0.f;
    }
    for (int idx = tid; idx < CPAD; idx += TPB) { sbm_s[idx] = 0.f; sbu_s[idx] = 0.f; }
    for (int idx = tid; idx < 5 * CPAD; idx += TPB) sWr_s[idx] = 0.f;
    __syncthreads();

    for (int idx = tid; idx < NW * NW; idx += TPB) {
        int k = idx / NW, j = idx % NW;
        int c = (j < JH) ? j : j + 3;
        sM1[k][c]  = Wm[idx];
        sM2[k][c]  = Wm[NW * NW + idx];
        sU1[k][c]  = Wu[idx];
        sU2[k][c]  = Wu[NW * NW + idx];
        sU34[k][c] = Wu[2 * NW * NW + idx] + Wu[3 * NW * NW + idx];
    }
    if (tid < NW) {
        sWf[tid] = Wf[tid]; sbf[tid] = bf[tid];
        int c = (tid < JH) ? tid : tid + 3;
        sbm_s[c] = bm[tid]; sbu_s[c] = bu[tid];
    }
    for (int idx = tid; idx < 5 * NW; idx += TPB) {
        int n = idx / NW, j = idx % NW;
        int c = (j < JH) ? j : j + 3;
        sWr_s[n * CPAD + c] = Wr[idx];
    }
    if (tid == 0) sbr = br[0];
    __syncthreads();

    const int gtid = blockIdx.x * TPB + tid;
    const int row  = gtid >> 1;
    if (row >= B) return;

    const int lane = tid & 31;
    const int srcE = lane & ~1, srcO = srcE | 1;
    const int half = tid & 1;
    const int jb   = half * 12;     // col base: 0 or 12 (both 16B-aligned)

    const float x0 = inp[row * 5 + 0];
    const float x1 = inp[row * 5 + 1];
    const float x2 = inp[row * 5 + 2];
    const float x3 = inp[row * 5 + 3];
    const float x4 = inp[row * 5 + 4];

    // packed biases for this half-row
    ull bm2[4], bu2[4]; float bm8, bu8;
    {
        const ulonglong2* p = reinterpret_cast<const ulonglong2*>(&sbm_s[jb]);
        bm2[0] = p[0].x; bm2[1] = p[0].y; bm2[2] = p[1].x; bm2[3] = p[1].y;
        bm8 = sbm_s[jb + 8];
        const ulonglong2* q = reinterpret_cast<const ulonglong2*>(&sbu_s[jb]);
        bu2[0] = q[0].x; bu2[1] = q[0].y; bu2[2] = q[1].x; bu2[3] = q[1].y;
        bu8 = sbu_s[jb + 8];
    }

    float o = half ? 0.f : sbr;
    float v[NW], m[JH];
    V9 Pa, Qa, Pb, Qb, Pc, Qc, Pd, Qd;
    V9 accA, accB, accC, accD;

#define ACC_INIT(A) do { A.q[0]=bu2[0]; A.q[1]=bu2[1]; A.q[2]=bu2[2]; A.q[3]=bu2[3]; A.s=bu8; } while(0)

    // ---- node a ----
    feat(v, x0, sWf, sbf);
    matvec_v<true>(Pa, v, sM1, jb);
    matvec_v<true>(Qa, v, sM2, jb);
    ACC_INIT(accA);
    matvec_v<false>(accA, v, sU34, jb);

    // ---- node b ----
    feat(v, x1, sWf, sbf);
    matvec_v<true>(Pb, v, sM1, jb);
    matvec_v<true>(Qb, v, sM2, jb);
    ACC_INIT(accB);
    matvec_v<false>(accB, v, sU34, jb);

    // ---- edges a-b ----
    mkmsg(m, Pa, Qb, bm2, bm8); matvec_m(accA, m, sU1, jb, srcE, srcO);   // Mab
    mkmsg(m, Pb, Qa, bm2, bm8); matvec_m(accB, m, sU1, jb, srcE, srcO);   // Mba

    // ---- node d ----
    feat(v, x3, sWf, sbf);
    matvec_v<true>(Pd, v, sM1, jb);
    matvec_v<true>(Qd, v, sM2, jb);
    ACC_INIT(accD);
    matvec_v<false>(accD, v, sU34, jb);

    // ---- edges a-d: retire node a ----
    mkmsg(m, Pa, Qd, bm2, bm8); matvec_m(accA, m, sU2, jb, srcE, srcO);   // Mad
    mkmsg(m, Pd, Qa, bm2, bm8); matvec_m(accD, m, sU2, jb, srcE, srcO);   // Mda
    o = fold(accA, &sWr_s[jb], o);                                        // accA dies

    // ---- node c ----
    feat(v, x2, sWf, sbf);
    matvec_v<true>(Pc, v, sM1, jb);
    matvec_v<true>(Qc, v, sM2, jb);
    ACC_INIT(accC);
    matvec_v<false>(accC, v, sU34, jb);

    // ---- edges b-c: retire node b ----
    mkmsg(m, Pb, Qc, bm2, bm8); matvec_m(accB, m, sU2, jb, srcE, srcO);   // Mbc
    mkmsg(m, Pc, Qb, bm2, bm8); matvec_m(accC, m, sU1, jb, srcE, srcO);   // Mcb
    o = fold(accB, &sWr_s[CPAD + jb], o);                                 // accB dies

    // ---- edges c-d: retire nodes c and d ----
    mkmsg(m, Pc, Qd, bm2, bm8); matvec_m(accC, m, sU2, jb, srcE, srcO);   // Mcd
    mkmsg(m, Pd, Qc, bm2, bm8); matvec_m(accD, m, sU1, jb, srcE, srcO);   // Mdc
    o = fold(accC, &sWr_s[2 * CPAD + jb], o);
    o = fold(accD, &sWr_s[3 * CPAD + jb], o);

    // ---- node e ----
    feat(v, x4, sWf, sbf);
    ACC_INIT(accA);                                                       // reuse accA
    matvec_v<false>(accA, v, sU34, jb);
    o = fold(accA, &sWr_s[4 * CPAD + jb], o);

#undef ACC_INIT

    // ---- pair reduction: even lane writes ----
    o += __shfl_xor_sync(0xffffffffu, o, 1);
    if (!half) out[row] = o;
}

extern "C" void kernel_launch(void* const* d_in, const int* in_sizes, int n_in,
                              void* d_out, int out_size)
{
    const float* inp = (const float*)d_in[0];
    const float* Wf  = (const float*)d_in[1];
    const float* bf  = (const float*)d_in[2];
    const float* Wm  = (const float*)d_in[3];
    const float* bm  = (const float*)d_in[4];
    const float* Wu  = (const float*)d_in[5];
    const float* bu  = (const float*)d_in[6];
    const float* Wr  = (const float*)d_in[7];
    const float* br  = (const float*)d_in[8];
    float* out = (float*)d_out;

    const int B = in_sizes[0] / 5;
    const long long threads = 2LL * B;
    const int grid = (int)((threads + TPB - 1) / TPB);
    mp_kernel<<<grid, TPB>>>(inp, Wf, bf, Wm, bm, Wu, bu, Wr, br, out, B);
}

// round 17
// speedup vs baseline: 1.5178x; 1.2948x over previous
#include <cuda_runtime.h>

#define NW   17
#define NK   18     // padded k rows (row 17 zeroed)
#define CPAD 24     // padded col stride: j<9 -> col j ; j>=9 -> col j+3 (12..20)
#define JH   9      // j elements per thread (half, padded)
#define TPB  128

// Single-instruction HW tanh (sm_75+). Max rel err ~2^-11, vs 1e-3 budget
// and 2.3e-7 measured with the 5-op ex2/rcp version -- 4000x margin.
// Replaces 2 MUFU + 3 FMA-pipe ops with 1 MUFU: ~800 issue slots/thread saved.
__device__ __forceinline__ float fast_tanh(float x) {
    float y; asm("tanh.approx.f32 %0, %1;" : "=f"(y) : "f"(x)); return y;
}

// Split-output matvec with FULL input vector v (no shuffles):
// acc[jj] (+)= sum_{k<17} v[k] * W[k][jb+jj]
template <bool INIT>
__device__ __forceinline__ void matvec_v(float acc[JH], const float v[NW],
                                         const float W[NK][CPAD], int jb) {
#pragma unroll
    for (int k = 0; k < NW; ++k) {
        const float vk = v[k];
        const float4* w4 = reinterpret_cast<const float4*>(&W[k][jb]);
        float4 w0 = w4[0], w1 = w4[1];
        float  w2 = W[k][jb + 8];
        if (INIT && k == 0) {
            acc[0] = vk * w0.x; acc[1] = vk * w0.y; acc[2] = vk * w0.z; acc[3] = vk * w0.w;
            acc[4] = vk * w1.x; acc[5] = vk * w1.y; acc[6] = vk * w1.z; acc[7] = vk * w1.w;
            acc[8] = vk * w2;
        } else {
            acc[0] = fmaf(vk, w0.x, acc[0]); acc[1] = fmaf(vk, w0.y, acc[1]);
            acc[2] = fmaf(vk, w0.z, acc[2]); acc[3] = fmaf(vk, w0.w, acc[3]);
            acc[4] = fmaf(vk, w1.x, acc[4]); acc[5] = fmaf(vk, w1.y, acc[5]);
            acc[6] = fmaf(vk, w1.z, acc[6]); acc[7] = fmaf(vk, w1.w, acc[7]);
            acc[8] = fmaf(vk, w2,   acc[8]);
        }
    }
}

// Split-output matvec with SPLIT input vector m (shuffle-gather from the pair):
// acc[jj] += sum_{k<18} m_full[k] * W[k][jb+jj], m_full gathered via shfl.
__device__ __forceinline__ void matvec_m(float acc[JH], const float mloc[JH],
                                         const float W[NK][CPAD], int jb,
                                         int srcE, int srcO) {
#pragma unroll
    for (int k = 0; k < NK; ++k) {
        const float mk = __shfl_sync(0xffffffffu, mloc[k % JH], (k < JH) ? srcE : srcO);
        const float4* w4 = reinterpret_cast<const float4*>(&W[k][jb]);
        float4 w0 = w4[0], w1 = w4[1];
        float  w2 = W[k][jb + 8];
        acc[0] = fmaf(mk, w0.x, acc[0]); acc[1] = fmaf(mk, w0.y, acc[1]);
        acc[2] = fmaf(mk, w0.z, acc[2]); acc[3] = fmaf(mk, w0.w, acc[3]);
        acc[4] = fmaf(mk, w1.x, acc[4]); acc[5] = fmaf(mk, w1.y, acc[5]);
        acc[6] = fmaf(mk, w1.z, acc[6]); acc[7] = fmaf(mk, w1.w, acc[7]);
        acc[8] = fmaf(mk, w2,   acc[8]);
    }
}

__device__ __forceinline__ void feat(float v[NW], float s,
                                     const float* sWf, const float* sbf) {
#pragma unroll
    for (int j = 0; j < NW; ++j) v[j] = fast_tanh(fmaf(s, sWf[j], sbf[j]));
}

// 2 threads per row (even: j=0..8, odd: j=9..16+pad). R14 structure verbatim
// (772us, DRAM=0.9%): uncapped (caps -> spills, R15), scalar matvecs
// (f32x2 packing -> pack-overhead regression, R16). Single change: HW tanh.
extern "C" __global__ void __launch_bounds__(TPB)
mp_kernel(const float* __restrict__ inp,
          const float* __restrict__ Wf,  const float* __restrict__ bf,
          const float* __restrict__ Wm,  const float* __restrict__ bm,
          const float* __restrict__ Wu,  const float* __restrict__ bu,
          const float* __restrict__ Wr,  const float* __restrict__ br,
          float* __restrict__ out, int B)
{
    __shared__ __align__(16) float sM1[NK][CPAD];   // Wm[:17]
    __shared__ __align__(16) float sM2[NK][CPAD];   // Wm[17:34]
    __shared__ __align__(16) float sU1[NK][CPAD];   // Wu[:17]
    __shared__ __align__(16) float sU2[NK][CPAD];   // Wu[17:34]
    __shared__ __align__(16) float sU34[NK][CPAD];  // Wu[34:51]+Wu[51:68]
    __shared__ float sWf[NW], sbf[NW];
    __shared__ __align__(16) float sbm_s[CPAD], sbu_s[CPAD], sWr_s[5 * CPAD];
    __shared__ float sbr;

    const int tid = threadIdx.x;

    // Zero everything padded first (pads MUST be 0 for correctness).
    for (int idx = tid; idx < NK * CPAD; idx += TPB) {
        int k = idx / CPAD, c = idx % CPAD;
        sM1[k][c] = 0.f; sM2[k][c] = 0.f;
        sU1[k][c] = 0.f; sU2[k][c] = 0.f; sU34[k][c] = 0.f;
    }
    for (int idx = tid; idx < CPAD; idx += TPB) { sbm_s[idx] = 0.f; sbu_s[idx] = 0.f; }
    for (int idx = tid; idx < 5 * CPAD; idx += TPB) sWr_s[idx] = 0.f;
    __syncthreads();

    for (int idx = tid; idx < NW * NW; idx += TPB) {
        int k = idx / NW, j = idx % NW;
        int c = (j < JH) ? j : j + 3;
        sM1[k][c]  = Wm[idx];
        sM2[k][c]  = Wm[NW * NW + idx];
        sU1[k][c]  = Wu[idx];
        sU2[k][c]  = Wu[NW * NW + idx];
        sU34[k][c] = Wu[2 * NW * NW + idx] + Wu[3 * NW * NW + idx];
    }
    if (tid < NW) {
        sWf[tid] = Wf[tid]; sbf[tid] = bf[tid];
        int c = (tid < JH) ? tid : tid + 3;
        sbm_s[c] = bm[tid]; sbu_s[c] = bu[tid];
    }
    for (int idx = tid; idx < 5 * NW; idx += TPB) {
        int n = idx / NW, j = idx % NW;
        int c = (j < JH) ? j : j + 3;
        sWr_s[n * CPAD + c] = Wr[idx];
    }
    if (tid == 0) sbr = br[0];
    __syncthreads();

    const int gtid = blockIdx.x * TPB + tid;
    const int row  = gtid >> 1;
    if (row >= B) return;

    const int lane = tid & 31;
    const int srcE = lane & ~1, srcO = srcE | 1;
    const int half = tid & 1;
    const int jb   = half * 12;     // col base: 0 (j 0..8) or 12 (j 9..16+pad)

    const float x0 = inp[row * 5 + 0];
    const float x1 = inp[row * 5 + 1];
    const float x2 = inp[row * 5 + 2];
    const float x3 = inp[row * 5 + 3];
    const float x4 = inp[row * 5 + 4];

    float o = half ? 0.f : sbr;
    float v[NW], m[JH];
    float Pa[JH], Qa[JH], Pb[JH], Qb[JH], Pc[JH], Qc[JH], Pd[JH], Qd[JH];
    float accA[JH], accB[JH], accC[JH], accD[JH];

    // ---- node a ----
    feat(v, x0, sWf, sbf);
    matvec_v<true>(Pa, v, sM1, jb);
    matvec_v<true>(Qa, v, sM2, jb);
#pragma unroll
    for (int jj = 0; jj < JH; ++jj) accA[jj] = sbu_s[jb + jj];
    matvec_v<false>(accA, v, sU34, jb);

    // ---- node b ----
    feat(v, x1, sWf, sbf);
    matvec_v<true>(Pb, v, sM1, jb);
    matvec_v<true>(Qb, v, sM2, jb);
#pragma unroll
    for (int jj = 0; jj < JH; ++jj) accB[jj] = sbu_s[jb + jj];
    matvec_v<false>(accB, v, sU34, jb);

    // ---- edges a-b ----
#pragma unroll
    for (int jj = 0; jj < JH; ++jj) m[jj] = fast_tanh(Pa[jj] + Qb[jj] + sbm_s[jb + jj]);
    matvec_m(accA, m, sU1, jb, srcE, srcO);                 // Mab
#pragma unroll
    for (int jj = 0; jj < JH; ++jj) m[jj] = fast_tanh(Pb[jj] + Qa[jj] + sbm_s[jb + jj]);
    matvec_m(accB, m, sU1, jb, srcE, srcO);                 // Mba

    // ---- node d ----
    feat(v, x3, sWf, sbf);
    matvec_v<true>(Pd, v, sM1, jb);
    matvec_v<true>(Qd, v, sM2, jb);
#pragma unroll
    for (int jj = 0; jj < JH; ++jj) accD[jj] = sbu_s[jb + jj];
    matvec_v<false>(accD, v, sU34, jb);

    // ---- edges a-d: retire node a ----
#pragma unroll
    for (int jj = 0; jj < JH; ++jj) m[jj] = fast_tanh(Pa[jj] + Qd[jj] + sbm_s[jb + jj]);
    matvec_m(accA, m, sU2, jb, srcE, srcO);                 // Mad (Pa dies)
#pragma unroll
    for (int jj = 0; jj < JH; ++jj) m[jj] = fast_tanh(Pd[jj] + Qa[jj] + sbm_s[jb + jj]);
    matvec_m(accD, m, sU2, jb, srcE, srcO);                 // Mda (Qa dies)
#pragma unroll
    for (int jj = 0; jj < JH; ++jj)
        o = fmaf(fast_tanh(accA[jj]), sWr_s[jb + jj], o);   // accA dies

    // ---- node c ----
    feat(v, x2, sWf, sbf);
    matvec_v<true>(Pc, v, sM1, jb);
    matvec_v<true>(Qc, v, sM2, jb);
#pragma unroll
    for (int jj = 0; jj < JH; ++jj) accC[jj] = sbu_s[jb + jj];
    matvec_v<false>(accC, v, sU34, jb);

    // ---- edges b-c: retire node b ----
#pragma unroll
    for (int jj = 0; jj < JH; ++jj) m[jj] = fast_tanh(Pb[jj] + Qc[jj] + sbm_s[jb + jj]);
    matvec_m(accB, m, sU2, jb, srcE, srcO);                 // Mbc (Pb dies)
#pragma unroll
    for (int jj = 0; jj < JH; ++jj) m[jj] = fast_tanh(Pc[jj] + Qb[jj] + sbm_s[jb + jj]);
    matvec_m(accC, m, sU1, jb, srcE, srcO);                 // Mcb (Qb dies)
#pragma unroll
    for (int jj = 0; jj < JH; ++jj)
        o = fmaf(fast_tanh(accB[jj]), sWr_s[CPAD + jb + jj], o);  // accB dies

    // ---- edges c-d: retire nodes c and d ----
#pragma unroll
    for (int jj = 0; jj < JH; ++jj) m[jj] = fast_tanh(Pc[jj] + Qd[jj] + sbm_s[jb + jj]);
    matvec_m(accC, m, sU2, jb, srcE, srcO);                 // Mcd
#pragma unroll
    for (int jj = 0; jj < JH; ++jj) m[jj] = fast_tanh(Pd[jj] + Qc[jj] + sbm_s[jb + jj]);
    matvec_m(accD, m, sU1, jb, srcE, srcO);                 // Mdc
#pragma unroll
    for (int jj = 0; jj < JH; ++jj)
        o = fmaf(fast_tanh(accC[jj]), sWr_s[2 * CPAD + jb + jj], o);
#pragma unroll
    for (int jj = 0; jj < JH; ++jj)
        o = fmaf(fast_tanh(accD[jj]), sWr_s[3 * CPAD + jb + jj], o);

    // ---- node e ----
    feat(v, x4, sWf, sbf);
#pragma unroll
    for (int jj = 0; jj < JH; ++jj) accA[jj] = sbu_s[jb + jj];   // reuse accA
    matvec_v<false>(accA, v, sU34, jb);
#pragma unroll
    for (int jj = 0; jj < JH; ++jj)
        o = fmaf(fast_tanh(accA[jj]), sWr_s[4 * CPAD + jb + jj], o);

    // ---- pair reduction: even lane writes ----
    o += __shfl_xor_sync(0xffffffffu, o, 1);
    if (!half) out[row] = o;
}

extern "C" void kernel_launch(void* const* d_in, const int* in_sizes, int n_in,
                              void* d_out, int out_size)
{
    const float* inp = (const float*)d_in[0];
    const float* Wf  = (const float*)d_in[1];
    const float* bf  = (const float*)d_in[2];
    const float* Wm  = (const float*)d_in[3];
    const float* bm  = (const float*)d_in[4];
    const float* Wu  = (const float*)d_in[5];
    const float* bu  = (const float*)d_in[6];
    const float* Wr  = (const float*)d_in[7];
    const float* br  = (const float*)d_in[8];
    float* out = (float*)d_out;

    const int B = in_sizes[0] / 5;
    const long long threads = 2LL * B;
    const int grid = (int)((threads + TPB - 1) / TPB);
    mp_kernel<<<grid, TPB>>>(inp, Wf, bf, Wm, bm, Wu, bu, Wr, br, out, B);
}